// round 12
// baseline (speedup 1.0000x reference)
#include <cuda_runtime.h>
#include <cuda_fp16.h>
#include <cstdint>
#include <math.h>

#define NTOK 4608
#define DIM 384
#define HGT 48
#define WID 48
#define NCELL 72
#define NHEAD 6
#define HD 64

// ---------------- scratch -----------------------------------------------------
__device__ float g_ab1[NCELL * 768];
__device__ float g_ab2[NCELL * 768];
__device__ float g_g1[NCELL * 384];
__device__ float g_g2[NCELL * 384];
__device__ float g_x[NTOK * DIM];

__device__ __align__(16) __half g_wqkv[1152 * 384];
__device__ __align__(16) __half g_wout[384 * 384];
__device__ __align__(16) __half g_wm1[1536 * 384];
__device__ __align__(16) __half g_wm2[384 * 1536];
__device__ __align__(16) __half g_h[NTOK * 384];
__device__ __align__(16) __half g_qkvh[NTOK * 1152];
__device__ __align__(16) __half g_attn[NTOK * 384];
__device__ __align__(16) __half g_mlp[NTOK * 1536];

// ---------------- helpers -----------------------------------------------------
#define GDC_WAIT() asm volatile("griddepcontrol.wait;" ::: "memory")

__device__ __forceinline__ uint32_t smem_u32(const void* p) {
    uint32_t a;
    asm("{ .reg .u64 t; cvta.to.shared.u64 t, %1; cvt.u32.u64 %0, t; }" : "=r"(a) : "l"(p));
    return a;
}
__device__ __forceinline__ void cp16(uint32_t dst, const void* src) {
    asm volatile("cp.async.ca.shared.global [%0], [%1], 16;" :: "r"(dst), "l"(src));
}
#define CP_COMMIT() asm volatile("cp.async.commit_group;" ::: "memory")
template <int N> __device__ __forceinline__ void cp_wait() {
    asm volatile("cp.async.wait_group %0;" :: "n"(N) : "memory");
}
__device__ __forceinline__ void ldsm_x4(uint32_t* r, uint32_t addr) {
    asm volatile("ldmatrix.sync.aligned.m8n8.x4.shared.b16 {%0,%1,%2,%3}, [%4];"
                 : "=r"(r[0]), "=r"(r[1]), "=r"(r[2]), "=r"(r[3]) : "r"(addr));
}
__device__ __forceinline__ void mma_f16(float* c, const uint32_t* a, const uint32_t* b) {
    asm volatile("mma.sync.aligned.m16n8k16.row.col.f32.f16.f16.f32 "
                 "{%0,%1,%2,%3}, {%4,%5,%6,%7}, {%8,%9}, {%0,%1,%2,%3};"
                 : "+f"(c[0]), "+f"(c[1]), "+f"(c[2]), "+f"(c[3])
                 : "r"(a[0]), "r"(a[1]), "r"(a[2]), "r"(a[3]), "r"(b[0]), "r"(b[1]));
}
__device__ __forceinline__ float tanh_fast(float x) {
    float y;
    asm("tanh.approx.f32 %0, %1;" : "=f"(y) : "f"(x));
    return y;
}

// ================ merged prep kernel ==========================================
#define PREP_SMEM (NCELL * DIM * 4)
#define CVT_F4_0 110592
#define CVT_F4_1 36864
#define CVT_F4_2 147456
#define CVT_F4_3 147456

__global__ void __launch_bounds__(256) prep_k(
    const float* __restrict__ cond,
    const float* __restrict__ a1v, const float* __restrict__ a1g,
    const float* __restrict__ a2v, const float* __restrict__ a2g,
    const float* __restrict__ g1v, const float* __restrict__ g1g,
    const float* __restrict__ g2v, const float* __restrict__ g2g,
    const float* __restrict__ w0, const float* __restrict__ w1,
    const float* __restrict__ w2, const float* __restrict__ w3) {
    const int tid = threadIdx.x;
    if (blockIdx.x >= 72) {
        const int cb = blockIdx.x - 72;
        #pragma unroll
        for (int t = 0; t < 4; t++) {
            int i4 = cb * 1024 + t * 256 + tid;
            const float* src; __half* dst; int li;
            if (i4 < CVT_F4_0)                      { src = w0; dst = g_wqkv; li = i4; }
            else if (i4 < CVT_F4_0 + CVT_F4_1)      { src = w1; dst = g_wout; li = i4 - CVT_F4_0; }
            else if (i4 < CVT_F4_0 + CVT_F4_1 + CVT_F4_2)
                                                    { src = w2; dst = g_wm1;  li = i4 - CVT_F4_0 - CVT_F4_1; }
            else                                    { src = w3; dst = g_wm2;  li = i4 - CVT_F4_0 - CVT_F4_1 - CVT_F4_2; }
            float4 v = ((const float4*)src)[li];
            __half2 h0 = __floats2half2_rn(v.x, v.y);
            __half2 h1 = __floats2half2_rn(v.z, v.w);
            uint2 u;
            u.x = *reinterpret_cast<uint32_t*>(&h0);
            u.y = *reinterpret_cast<uint32_t*>(&h1);
            *reinterpret_cast<uint2*>(dst + (size_t)li * 4) = u;
        }
        return;
    }
    extern __shared__ float sc[];
    for (int i = tid; i < NCELL * DIM; i += 256) {
        float v = cond[i];
        sc[i] = v / (1.0f + __expf(-v));
    }
    __syncthreads();

    const int r0 = blockIdx.x * 32;
    const int w = tid >> 5, lane = tid & 31;
    const float* v; const float* g; float* out; int R; int rb;
    if (r0 < 768)       { v = a1v; g = a1g; out = g_ab1; R = 768; rb = r0; }
    else if (r0 < 1536) { v = a2v; g = a2g; out = g_ab2; R = 768; rb = r0 - 768; }
    else if (r0 < 1920) { v = g1v; g = g1g; out = g_g1;  R = 384; rb = r0 - 1536; }
    else                { v = g2v; g = g2g; out = g_g2;  R = 384; rb = r0 - 1920; }

    float vr[4][12];
    float sr[4];
    #pragma unroll
    for (int j = 0; j < 4; j++) {
        const int rl = rb + w * 4 + j;
        const float* row = v + (size_t)rl * DIM;
        float n = 0.0f;
        #pragma unroll
        for (int q = 0; q < 12; q++) {
            float t = row[lane + 32 * q];
            vr[j][q] = t;
            n += t * t;
        }
        #pragma unroll
        for (int o = 16; o; o >>= 1) n += __shfl_xor_sync(0xffffffffu, n, o);
        sr[j] = g[rl] * rsqrtf(n);
    }
    for (int cell = 0; cell < NCELL; cell++) {
        const float* scc = sc + cell * DIM;
        float p[4] = {0.0f, 0.0f, 0.0f, 0.0f};
        #pragma unroll
        for (int q = 0; q < 12; q++) {
            float s = scc[lane + 32 * q];
            #pragma unroll
            for (int j = 0; j < 4; j++) p[j] += s * vr[j][q];
        }
        #pragma unroll
        for (int j = 0; j < 4; j++) {
            #pragma unroll
            for (int o = 16; o; o >>= 1) p[j] += __shfl_xor_sync(0xffffffffu, p[j], o);
        }
        if (lane < 4) out[cell * R + rb + w * 4 + lane] = p[lane] * sr[lane];
    }
}

// ---------------- adaLN, warp-per-token -> fp16 --------------------------------
__global__ void __launch_bounds__(256) adaln_k(const float* __restrict__ x,
                                               const float* __restrict__ gamma,
                                               const float* __restrict__ beta,
                                               const float* __restrict__ ab) {
    GDC_WAIT();
    const int t = blockIdx.x * 8 + (threadIdx.x >> 5);
    const int lane = threadIdx.x & 31;
    const float* xr = x + (size_t)t * DIM;

    float2 v[6];
    float s = 0.0f;
    #pragma unroll
    for (int j = 0; j < 6; j++) {
        v[j] = *(const float2*)(xr + j * 64 + lane * 2);
        s += v[j].x + v[j].y;
    }
    #pragma unroll
    for (int o = 16; o; o >>= 1) s += __shfl_xor_sync(0xffffffffu, s, o);
    const float mu = s * (1.0f / 384.0f);

    float q = 0.0f;
    #pragma unroll
    for (int j = 0; j < 6; j++) {
        float dx = v[j].x - mu, dy = v[j].y - mu;
        q += dx * dx + dy * dy;
    }
    #pragma unroll
    for (int o = 16; o; o >>= 1) q += __shfl_xor_sync(0xffffffffu, q, o);
    const float rstd = rsqrtf(q * (1.0f / 384.0f) + 1e-6f);

    const int b = t / (HGT * WID);
    const int rem = t % (HGT * WID);
    const int cell = b * 36 + ((rem / WID) >> 3) * 6 + ((rem % WID) >> 3);
    const float* abp = ab + cell * 768;

    #pragma unroll
    for (int j = 0; j < 6; j++) {
        const int c = j * 64 + lane * 2;
        float2 gm = *(const float2*)(gamma + c);
        float2 bt = *(const float2*)(beta + c);
        float2 aa = *(const float2*)(abp + c);
        float2 bb = *(const float2*)(abp + 384 + c);
        float y0 = (v[j].x - mu) * rstd * gm.x + bt.x;
        float y1 = (v[j].y - mu) * rstd * gm.y + bt.y;
        y0 = y0 * (1.0f + aa.x) + bb.x;
        y1 = y1 * (1.0f + aa.y) + bb.y;
        *(__half2*)(g_h + (size_t)t * DIM + c) = __floats2half2_rn(y0, y1);
    }
}

// ================= cp.async 3-stage fp16 GEMM ==================================
#define PITCH 40
#define TILE_B 10240
#define BUF_B  20480
#define SMEM_TOT (3 * BUF_B)

template <int EPI>
__global__ void __launch_bounds__(256)
hgemm_k(const __half* __restrict__ Ap, const __half* __restrict__ Wp,
        const float* __restrict__ bias, float* __restrict__ C,
        int K, int M,
        const float* __restrict__ res, const float* __restrict__ gate,
        __half* __restrict__ Oh) {
    extern __shared__ char smem[];
    const uint32_t sbase = smem_u32(smem);
    const int tid = threadIdx.x;
    const int lane = tid & 31;
    const int w = tid >> 5;
    const int wr = w >> 2;
    const int wc = w & 3;
    const int row0 = blockIdx.y * 128;
    const int col0 = blockIdx.x * 128;

    float acc[4][4][4];
    #pragma unroll
    for (int i = 0; i < 4; i++)
        #pragma unroll
        for (int j = 0; j < 4; j++)
            #pragma unroll
            for (int q = 0; q < 4; q++) acc[i][j][q] = 0.0f;

    const int ldrow = tid >> 1;
    const int lc = (tid & 1) * 32;
    const char* srcA = (const char*)(Ap + (size_t)(row0 + ldrow) * K) + lc;
    const char* srcW = (const char*)(Wp + (size_t)(col0 + ldrow) * K) + lc;
    const uint32_t dbase = sbase + ldrow * (PITCH * 2) + lc;

    const int nCh = K >> 5;

    auto issue = [&](int c) {
        const int bo = (c % 3) * BUF_B;
        const int go = c * 64;
        #pragma unroll
        for (int j = 0; j < 2; j++) {
            cp16(dbase + bo + 0 * TILE_B + j * 16, srcA + go + j * 16);
            cp16(dbase + bo + 1 * TILE_B + j * 16, srcW + go + j * 16);
        }
    };

    GDC_WAIT();
    issue(0); CP_COMMIT();
    if (nCh > 1) issue(1);
    CP_COMMIT();

    const int arow = lane & 15;
    const int acolh = (lane >> 4) << 3;
    const int bnt2 = lane >> 4;
    const int bkh = (lane >> 3) & 1;
    const int brow = lane & 7;

    for (int c = 0; c < nCh; c++) {
        cp_wait<1>();
        __syncthreads();
        if (c + 2 < nCh) issue(c + 2);
        CP_COMMIT();

        const uint32_t bo = sbase + (c % 3) * BUF_B;
        const uint32_t uA = bo, uB = bo + TILE_B;

        uint32_t ah[2][4][4], bh[2][4][2];
        #pragma unroll
        for (int ks = 0; ks < 2; ks++) {
            const int k0 = ks * 16;
            #pragma unroll
            for (int mt = 0; mt < 4; mt++) {
                uint32_t off = (uint32_t)((wr * 64 + mt * 16 + arow) * PITCH + k0 + acolh) * 2;
                ldsm_x4(ah[ks][mt], uA + off);
            }
            #pragma unroll
            for (int ntp = 0; ntp < 2; ntp++) {
                uint32_t off = (uint32_t)((wc * 32 + (ntp * 2 + bnt2) * 8 + brow) * PITCH
                                          + k0 + bkh * 8) * 2;
                ldsm_x4(&bh[ks][ntp * 2][0], uB + off);
            }
        }
        #pragma unroll
        for (int ks = 0; ks < 2; ks++)
            #pragma unroll
            for (int mt = 0; mt < 4; mt++)
                #pragma unroll
                for (int nt = 0; nt < 4; nt++)
                    mma_f16(acc[mt][nt], ah[ks][mt], bh[ks][nt]);
    }

    #pragma unroll
    for (int mt = 0; mt < 4; mt++) {
        #pragma unroll
        for (int half_ = 0; half_ < 2; half_++) {
            const int r = row0 + wr * 64 + mt * 16 + (lane >> 2) + half_ * 8;
            const float* gt = nullptr;
            const float* rs = nullptr;
            if (EPI >= 2) {
                int b = r / (HGT * WID);
                int rem = r % (HGT * WID);
                int hh = rem / WID, ww = rem % WID;
                gt = gate + (b * 36 + (hh >> 3) * 6 + (ww >> 3)) * 384;
                rs = res + (size_t)r * 384;
            }
            #pragma unroll
            for (int nt = 0; nt < 4; nt++) {
                const int cc = col0 + wc * 32 + nt * 8 + (lane & 3) * 2;
                float v0 = acc[mt][nt][half_ * 2 + 0] + bias[cc];
                float v1 = acc[mt][nt][half_ * 2 + 1] + bias[cc + 1];
                if (EPI == 1) {
                    float x3 = v0 * v0 * v0;
                    v0 = 0.5f * v0 * (1.0f + tanh_fast(0.7978845608028654f * (v0 + 0.044715f * x3)));
                    x3 = v1 * v1 * v1;
                    v1 = 0.5f * v1 * (1.0f + tanh_fast(0.7978845608028654f * (v1 + 0.044715f * x3)));
                }
                if (EPI <= 1) {
                    *(__half2*)(Oh + (size_t)r * M + cc) = __floats2half2_rn(v0, v1);
                } else {
                    float2 o;
                    o.x = rs[cc]     + v0 * gt[cc];
                    o.y = rs[cc + 1] + v1 * gt[cc + 1];
                    *(float2*)(C + (size_t)r * 384 + cc) = o;
                }
            }
        }
    }
}

// ================= tiled neighborhood attention (fp16 smem) ====================
// 256 threads (8 warps x 8 tokens), fp16 K/V in smem, pitch 68 halves (136B rows)
#define NPITCH 68
#define NAT_KVH (196 * NPITCH)                  // halves per matrix
#define NAT_SK 0
#define NAT_SV (NAT_KVH * 2)                    // byte offsets
#define NAT_SQ (NAT_SV + NAT_KVH * 2)           // 8 warps x 128B
#define NAT_SW (NAT_SQ + 8 * 128)               // 8 warps x 256B (floats)
#define NAT_SMEM (NAT_SW + 8 * 256)

__global__ void __launch_bounds__(256) natten_k() {
    extern __shared__ char nsm[];
    __half* sK = (__half*)(nsm + NAT_SK);
    __half* sV = (__half*)(nsm + NAT_SV);

    const int tile = blockIdx.x;
    const int head = blockIdx.y;
    const int b = tile / 36;
    const int trm = tile % 36;
    const int t0h = (trm / 6) * 8;
    const int t0w = (trm % 6) * 8;
    const int rlo = max(0, t0h - 3);
    const int rhi = min(HGT - 1, t0h + 10);
    const int clo = max(0, t0w - 3);
    const int chi = min(WID - 1, t0w + 10);
    const int nr = rhi - rlo + 1;
    const int nc = chi - clo + 1;

    GDC_WAIT();
    const int tid = threadIdx.x;
    const int tot = nr * nc * 32;          // half2 units per matrix
    for (int i = tid; i < tot; i += 256) {
        int li = i >> 5;
        int d2 = (i & 31);                 // half2 index
        int row = li / nc, col = li % nc;
        size_t gbase = (size_t)((b * HGT + rlo + row) * WID + clo + col) * 1152 + head * HD + d2 * 2;
        int so = (row * 14 + col) * NPITCH + d2 * 2;
        *(__half2*)(sK + so) = *(const __half2*)(g_qkvh + gbase + 384);
        *(__half2*)(sV + so) = *(const __half2*)(g_qkvh + gbase + 768);
    }
    __syncthreads();

    const int wid = tid >> 5;
    const int lane = tid & 31;
    __half* q = (__half*)(nsm + NAT_SQ + wid * 128);
    float* wb = (float*)(nsm + NAT_SW + wid * 256);
    const int off1 = (lane / 7) * 14 + lane % 7;
    const int nb2 = lane + 32;
    const int off2 = (nb2 / 7) * 14 + nb2 % 7;
    const bool v2ok = nb2 < 49;

    for (int tt = wid * 8; tt < wid * 8 + 8; tt++) {
        const int tr = tt >> 3, tc = tt & 7;
        const int gr = t0h + tr, gc = t0w + tc;
        const int t = (b * HGT + gr) * WID + gc;
        const int sh = min(max(gr - 3, 0), HGT - 7) - rlo;
        const int sw = min(max(gc - 3, 0), WID - 7) - clo;
        const int base = sh * 14 + sw;

        // stage q (64 halves) for broadcast reads
        *(__half2*)(q + lane * 2) = *(const __half2*)(g_qkvh + (size_t)t * 1152 + head * HD + lane * 2);
        __syncwarp();

        float a1 = 0.0f, a2 = 0.0f;
        const uint2* qv = (const uint2*)q;
        const uint2* k1 = (const uint2*)(sK + (base + off1) * NPITCH);
        const uint2* k2 = (const uint2*)(sK + (base + off2) * NPITCH);
        #pragma unroll
        for (int d = 0; d < 16; d++) {
            uint2 qu = qv[d];
            uint2 u1 = k1[d];
            uint2 u2 = k2[d];
            float2 qa = __half22float2(*(const __half2*)&qu.x);
            float2 qb = __half22float2(*(const __half2*)&qu.y);
            float2 x1a = __half22float2(*(const __half2*)&u1.x);
            float2 x1b = __half22float2(*(const __half2*)&u1.y);
            float2 x2a = __half22float2(*(const __half2*)&u2.x);
            float2 x2b = __half22float2(*(const __half2*)&u2.y);
            a1 += qa.x * x1a.x + qa.y * x1a.y + qb.x * x1b.x + qb.y * x1b.y;
            a2 += qa.x * x2a.x + qa.y * x2a.y + qb.x * x2b.x + qb.y * x2b.y;
        }
        a1 *= 0.125f;
        a2 = v2ok ? a2 * 0.125f : -1e30f;

        float m = fmaxf(a1, a2);
        #pragma unroll
        for (int o = 16; o; o >>= 1) m = fmaxf(m, __shfl_xor_sync(0xffffffffu, m, o));
        float e1 = __expf(a1 - m);
        float e2 = v2ok ? __expf(a2 - m) : 0.0f;
        float s = e1 + e2;
        #pragma unroll
        for (int o = 16; o; o >>= 1) s += __shfl_xor_sync(0xffffffffu, s, o);
        float inv = 1.0f / s;
        wb[lane] = e1;
        wb[32 + lane] = e2;
        __syncwarp();

        // AV: lane owns dims 2*lane, 2*lane+1
        float o0 = 0.0f, o1 = 0.0f;
        #pragma unroll
        for (int nb = 0; nb < 49; nb++) {
            const int off = (nb / 7) * 14 + nb % 7;
            float wv = wb[nb];
            float2 vv = __half22float2(*(const __half2*)(sV + (base + off) * NPITCH + lane * 2));
            o0 += wv * vv.x;
            o1 += wv * vv.y;
        }
        o0 *= inv; o1 *= inv;
        *(__half2*)(g_attn + (size_t)t * DIM + head * HD + lane * 2) = __floats2half2_rn(o0, o1);
        __syncwarp();
    }
}

// ---------------- launch ------------------------------------------------------
template <typename F, typename... Args>
static void launch_pdl(F f, dim3 g, dim3 b, size_t smem, Args... args) {
    cudaLaunchConfig_t cfg = {};
    cfg.gridDim = g;
    cfg.blockDim = b;
    cfg.dynamicSmemBytes = smem;
    cfg.stream = 0;
    cudaLaunchAttribute at[1];
    at[0].id = cudaLaunchAttributeProgrammaticStreamSerialization;
    at[0].val.programmaticStreamSerializationAllowed = 1;
    cfg.attrs = at;
    cfg.numAttrs = 1;
    cudaLaunchKernelEx(&cfg, f, args...);
}

extern "C" void kernel_launch(void* const* d_in, const int* in_sizes, int n_in,
                              void* d_out, int out_size) {
    const float* x       = (const float*)d_in[0];
    const float* cond    = (const float*)d_in[1];
    const float* ln1_g   = (const float*)d_in[2];
    const float* ln1_b   = (const float*)d_in[3];
    const float* ada1_v  = (const float*)d_in[4];
    const float* ada1_g  = (const float*)d_in[5];
    const float* ln2_g   = (const float*)d_in[6];
    const float* ln2_b   = (const float*)d_in[7];
    const float* ada2_v  = (const float*)d_in[8];
    const float* ada2_g  = (const float*)d_in[9];
    const float* gate1_v = (const float*)d_in[10];
    const float* gate1_g = (const float*)d_in[11];
    const float* gate2_v = (const float*)d_in[12];
    const float* gate2_g = (const float*)d_in[13];
    const float* w_qkv   = (const float*)d_in[14];
    const float* b_qkv   = (const float*)d_in[15];
    const float* w_out   = (const float*)d_in[16];
    const float* b_out   = (const float*)d_in[17];
    const float* w_mlp1  = (const float*)d_in[18];
    const float* b_mlp1  = (const float*)d_in[19];
    const float* w_mlp2  = (const float*)d_in[20];
    const float* b_mlp2  = (const float*)d_in[21];
    float* out = (float*)d_out;

    float *p_ab1, *p_g1, *p_ab2, *p_g2, *p_x;
    __half *p_h, *p_qkvh, *p_attn, *p_mlp, *p_wq, *p_wo, *p_w1, *p_w2;
    cudaGetSymbolAddress((void**)&p_ab1, g_ab1);
    cudaGetSymbolAddress((void**)&p_ab2, g_ab2);
    cudaGetSymbolAddress((void**)&p_g1, g_g1);
    cudaGetSymbolAddress((void**)&p_g2, g_g2);
    cudaGetSymbolAddress((void**)&p_x, g_x);
    cudaGetSymbolAddress((void**)&p_h, g_h);
    cudaGetSymbolAddress((void**)&p_qkvh, g_qkvh);
    cudaGetSymbolAddress((void**)&p_attn, g_attn);
    cudaGetSymbolAddress((void**)&p_mlp, g_mlp);
    cudaGetSymbolAddress((void**)&p_wq, g_wqkv);
    cudaGetSymbolAddress((void**)&p_wo, g_wout);
    cudaGetSymbolAddress((void**)&p_w1, g_wm1);
    cudaGetSymbolAddress((void**)&p_w2, g_wm2);

    cudaFuncSetAttribute(prep_k, cudaFuncAttributeMaxDynamicSharedMemorySize, PREP_SMEM);
    cudaFuncSetAttribute(hgemm_k<0>, cudaFuncAttributeMaxDynamicSharedMemorySize, SMEM_TOT);
    cudaFuncSetAttribute(hgemm_k<1>, cudaFuncAttributeMaxDynamicSharedMemorySize, SMEM_TOT);
    cudaFuncSetAttribute(hgemm_k<2>, cudaFuncAttributeMaxDynamicSharedMemorySize, SMEM_TOT);
    cudaFuncSetAttribute(hgemm_k<3>, cudaFuncAttributeMaxDynamicSharedMemorySize, SMEM_TOT);
    cudaFuncSetAttribute(natten_k, cudaFuncAttributeMaxDynamicSharedMemorySize, NAT_SMEM);

    prep_k<<<72 + 432, 256, PREP_SMEM>>>(cond, ada1_v, ada1_g, ada2_v, ada2_g,
                                         gate1_v, gate1_g, gate2_v, gate2_g,
                                         w_qkv, w_out, w_mlp1, w_mlp2);

    const float* nullf = nullptr;
    __half* nullh = nullptr;

    launch_pdl(adaln_k, dim3(NTOK / 8), dim3(256), 0, x, ln1_g, ln1_b, (const float*)p_ab1);
    launch_pdl(hgemm_k<0>, dim3(1152 / 128, NTOK / 128), dim3(256), (size_t)SMEM_TOT,
               (const __half*)p_h, (const __half*)p_wq, b_qkv, (float*)nullptr, 384, 1152,
               nullf, nullf, p_qkvh);
    launch_pdl(natten_k, dim3(72, NHEAD), dim3(256), (size_t)NAT_SMEM);
    launch_pdl(hgemm_k<2>, dim3(384 / 128, NTOK / 128), dim3(256), (size_t)SMEM_TOT,
               (const __half*)p_attn, (const __half*)p_wo, b_out, p_x, 384, 384,
               x, (const float*)p_g1, nullh);
    launch_pdl(adaln_k, dim3(NTOK / 8), dim3(256), 0, (const float*)p_x, ln2_g, ln2_b,
               (const float*)p_ab2);
    launch_pdl(hgemm_k<1>, dim3(1536 / 128, NTOK / 128), dim3(256), (size_t)SMEM_TOT,
               (const __half*)p_h, (const __half*)p_w1, b_mlp1, (float*)nullptr, 384, 1536,
               nullf, nullf, p_mlp);
    launch_pdl(hgemm_k<3>, dim3(384 / 128, NTOK / 128), dim3(256), (size_t)SMEM_TOT,
               (const __half*)p_mlp, (const __half*)p_w2, b_mlp2, out, 1536, 384,
               (const float*)p_x, (const float*)p_g2, nullh);
}

// round 13
// speedup vs baseline: 1.0199x; 1.0199x over previous
#include <cuda_runtime.h>
#include <cuda_fp16.h>
#include <cstdint>
#include <math.h>

#define NTOK 4608
#define DIM 384
#define HGT 48
#define WID 48
#define NCELL 72
#define NHEAD 6
#define HD 64

// ---------------- scratch -----------------------------------------------------
__device__ float g_ab1[NCELL * 768];
__device__ float g_ab2[NCELL * 768];
__device__ float g_g1[NCELL * 384];
__device__ float g_g2[NCELL * 384];
__device__ float g_x[NTOK * DIM];

__device__ __align__(16) __half g_wqkv[1152 * 384];
__device__ __align__(16) __half g_wout[384 * 384];
__device__ __align__(16) __half g_wm1[1536 * 384];
__device__ __align__(16) __half g_wm2[384 * 1536];
__device__ __align__(16) __half g_h[NTOK * 384];
__device__ __align__(16) __half g_qkvh[NTOK * 1152];
__device__ __align__(16) __half g_attn[NTOK * 384];
__device__ __align__(16) __half g_mlp[NTOK * 1536];

// ---------------- helpers -----------------------------------------------------
#define GDC_WAIT() asm volatile("griddepcontrol.wait;" ::: "memory")

__device__ __forceinline__ uint32_t smem_u32(const void* p) {
    uint32_t a;
    asm("{ .reg .u64 t; cvta.to.shared.u64 t, %1; cvt.u32.u64 %0, t; }" : "=r"(a) : "l"(p));
    return a;
}
__device__ __forceinline__ void cp16(uint32_t dst, const void* src) {
    asm volatile("cp.async.ca.shared.global [%0], [%1], 16;" :: "r"(dst), "l"(src));
}
#define CP_COMMIT() asm volatile("cp.async.commit_group;" ::: "memory")
template <int N> __device__ __forceinline__ void cp_wait() {
    asm volatile("cp.async.wait_group %0;" :: "n"(N) : "memory");
}
__device__ __forceinline__ void ldsm_x4(uint32_t* r, uint32_t addr) {
    asm volatile("ldmatrix.sync.aligned.m8n8.x4.shared.b16 {%0,%1,%2,%3}, [%4];"
                 : "=r"(r[0]), "=r"(r[1]), "=r"(r[2]), "=r"(r[3]) : "r"(addr));
}
__device__ __forceinline__ void mma_f16(float* c, const uint32_t* a, const uint32_t* b) {
    asm volatile("mma.sync.aligned.m16n8k16.row.col.f32.f16.f16.f32 "
                 "{%0,%1,%2,%3}, {%4,%5,%6,%7}, {%8,%9}, {%0,%1,%2,%3};"
                 : "+f"(c[0]), "+f"(c[1]), "+f"(c[2]), "+f"(c[3])
                 : "r"(a[0]), "r"(a[1]), "r"(a[2]), "r"(a[3]), "r"(b[0]), "r"(b[1]));
}
__device__ __forceinline__ float tanh_fast(float x) {
    float y;
    asm("tanh.approx.f32 %0, %1;" : "=f"(y) : "f"(x));
    return y;
}

// ================ merged prep kernel ==========================================
#define PREP_SMEM (NCELL * DIM * 4)
#define CVT_F4_0 110592
#define CVT_F4_1 36864
#define CVT_F4_2 147456
#define CVT_F4_3 147456

__global__ void __launch_bounds__(256) prep_k(
    const float* __restrict__ cond,
    const float* __restrict__ a1v, const float* __restrict__ a1g,
    const float* __restrict__ a2v, const float* __restrict__ a2g,
    const float* __restrict__ g1v, const float* __restrict__ g1g,
    const float* __restrict__ g2v, const float* __restrict__ g2g,
    const float* __restrict__ w0, const float* __restrict__ w1,
    const float* __restrict__ w2, const float* __restrict__ w3) {
    const int tid = threadIdx.x;
    if (blockIdx.x >= 72) {
        const int cb = blockIdx.x - 72;
        #pragma unroll
        for (int t = 0; t < 4; t++) {
            int i4 = cb * 1024 + t * 256 + tid;
            const float* src; __half* dst; int li;
            if (i4 < CVT_F4_0)                      { src = w0; dst = g_wqkv; li = i4; }
            else if (i4 < CVT_F4_0 + CVT_F4_1)      { src = w1; dst = g_wout; li = i4 - CVT_F4_0; }
            else if (i4 < CVT_F4_0 + CVT_F4_1 + CVT_F4_2)
                                                    { src = w2; dst = g_wm1;  li = i4 - CVT_F4_0 - CVT_F4_1; }
            else                                    { src = w3; dst = g_wm2;  li = i4 - CVT_F4_0 - CVT_F4_1 - CVT_F4_2; }
            float4 v = ((const float4*)src)[li];
            __half2 h0 = __floats2half2_rn(v.x, v.y);
            __half2 h1 = __floats2half2_rn(v.z, v.w);
            uint2 u;
            u.x = *reinterpret_cast<uint32_t*>(&h0);
            u.y = *reinterpret_cast<uint32_t*>(&h1);
            *reinterpret_cast<uint2*>(dst + (size_t)li * 4) = u;
        }
        return;
    }
    extern __shared__ float sc[];
    for (int i = tid; i < NCELL * DIM; i += 256) {
        float v = cond[i];
        sc[i] = v / (1.0f + __expf(-v));
    }
    __syncthreads();

    const int r0 = blockIdx.x * 32;
    const int w = tid >> 5, lane = tid & 31;
    const float* v; const float* g; float* out; int R; int rb;
    if (r0 < 768)       { v = a1v; g = a1g; out = g_ab1; R = 768; rb = r0; }
    else if (r0 < 1536) { v = a2v; g = a2g; out = g_ab2; R = 768; rb = r0 - 768; }
    else if (r0 < 1920) { v = g1v; g = g1g; out = g_g1;  R = 384; rb = r0 - 1536; }
    else                { v = g2v; g = g2g; out = g_g2;  R = 384; rb = r0 - 1920; }

    float vr[4][12];
    float sr[4];
    #pragma unroll
    for (int j = 0; j < 4; j++) {
        const int rl = rb + w * 4 + j;
        const float* row = v + (size_t)rl * DIM;
        float n = 0.0f;
        #pragma unroll
        for (int q = 0; q < 12; q++) {
            float t = row[lane + 32 * q];
            vr[j][q] = t;
            n += t * t;
        }
        #pragma unroll
        for (int o = 16; o; o >>= 1) n += __shfl_xor_sync(0xffffffffu, n, o);
        sr[j] = g[rl] * rsqrtf(n);
    }
    for (int cell = 0; cell < NCELL; cell++) {
        const float* scc = sc + cell * DIM;
        float p[4] = {0.0f, 0.0f, 0.0f, 0.0f};
        #pragma unroll
        for (int q = 0; q < 12; q++) {
            float s = scc[lane + 32 * q];
            #pragma unroll
            for (int j = 0; j < 4; j++) p[j] += s * vr[j][q];
        }
        #pragma unroll
        for (int j = 0; j < 4; j++) {
            #pragma unroll
            for (int o = 16; o; o >>= 1) p[j] += __shfl_xor_sync(0xffffffffu, p[j], o);
        }
        if (lane < 4) out[cell * R + rb + w * 4 + lane] = p[lane] * sr[lane];
    }
}

// ---------------- adaLN, warp-per-token -> fp16 --------------------------------
__global__ void __launch_bounds__(256) adaln_k(const float* __restrict__ x,
                                               const float* __restrict__ gamma,
                                               const float* __restrict__ beta,
                                               const float* __restrict__ ab) {
    GDC_WAIT();
    const int t = blockIdx.x * 8 + (threadIdx.x >> 5);
    const int lane = threadIdx.x & 31;
    const float* xr = x + (size_t)t * DIM;

    float2 v[6];
    float s = 0.0f;
    #pragma unroll
    for (int j = 0; j < 6; j++) {
        v[j] = *(const float2*)(xr + j * 64 + lane * 2);
        s += v[j].x + v[j].y;
    }
    #pragma unroll
    for (int o = 16; o; o >>= 1) s += __shfl_xor_sync(0xffffffffu, s, o);
    const float mu = s * (1.0f / 384.0f);

    float q = 0.0f;
    #pragma unroll
    for (int j = 0; j < 6; j++) {
        float dx = v[j].x - mu, dy = v[j].y - mu;
        q += dx * dx + dy * dy;
    }
    #pragma unroll
    for (int o = 16; o; o >>= 1) q += __shfl_xor_sync(0xffffffffu, q, o);
    const float rstd = rsqrtf(q * (1.0f / 384.0f) + 1e-6f);

    const int b = t / (HGT * WID);
    const int rem = t % (HGT * WID);
    const int cell = b * 36 + ((rem / WID) >> 3) * 6 + ((rem % WID) >> 3);
    const float* abp = ab + cell * 768;

    #pragma unroll
    for (int j = 0; j < 6; j++) {
        const int c = j * 64 + lane * 2;
        float2 gm = *(const float2*)(gamma + c);
        float2 bt = *(const float2*)(beta + c);
        float2 aa = *(const float2*)(abp + c);
        float2 bb = *(const float2*)(abp + 384 + c);
        float y0 = (v[j].x - mu) * rstd * gm.x + bt.x;
        float y1 = (v[j].y - mu) * rstd * gm.y + bt.y;
        y0 = y0 * (1.0f + aa.x) + bb.x;
        y1 = y1 * (1.0f + aa.y) + bb.y;
        *(__half2*)(g_h + (size_t)t * DIM + c) = __floats2half2_rn(y0, y1);
    }
}

// ================= cp.async 3-stage fp16 GEMM, 64x128 tiles ====================
// 8 warps as 2x4, warp tile 32x32, acc 32 regs -> 2 CTAs/SM
#define PITCH 40                 // fp16 per SMEM row (32 + 8 pad), 80 B
#define TILE_A_B 5120            // 64 * 80
#define TILE_W_B 10240           // 128 * 80
#define BUF_B  15360
#define SMEM_TOT (3 * BUF_B)     // 46080

template <int EPI>
__global__ void __launch_bounds__(256, 2)
hgemm_k(const __half* __restrict__ Ap, const __half* __restrict__ Wp,
        const float* __restrict__ bias, float* __restrict__ C,
        int K, int M,
        const float* __restrict__ res, const float* __restrict__ gate,
        __half* __restrict__ Oh) {
    extern __shared__ char smem[];
    const uint32_t sbase = smem_u32(smem);
    const int tid = threadIdx.x;
    const int lane = tid & 31;
    const int w = tid >> 5;
    const int wr = w >> 2;           // 0..1 (32-row band)
    const int wc = w & 3;            // 0..3 (32-col band)
    const int row0 = blockIdx.y * 64;
    const int col0 = blockIdx.x * 128;

    float acc[2][4][4];
    #pragma unroll
    for (int i = 0; i < 2; i++)
        #pragma unroll
        for (int j = 0; j < 4; j++)
            #pragma unroll
            for (int q = 0; q < 4; q++) acc[i][j][q] = 0.0f;

    // loaders: A 64 rows x 64B (256 chunks), W 128 rows x 64B (512 chunks)
    const int arow_ld = tid >> 2;            // 0..63
    const int acol_ld = (tid & 3) * 16;      // byte in row
    const char* srcA = (const char*)(Ap + (size_t)(row0 + arow_ld) * K) + acol_ld;
    const char* srcW0 = (const char*)(Wp + (size_t)(col0 + arow_ld) * K) + acol_ld;
    const char* srcW1 = (const char*)(Wp + (size_t)(col0 + arow_ld + 64) * K) + acol_ld;
    const uint32_t dA = sbase + arow_ld * 80 + acol_ld;
    const uint32_t dW0 = sbase + TILE_A_B + arow_ld * 80 + acol_ld;
    const uint32_t dW1 = dW0 + 64 * 80;

    const int nCh = K >> 5;

    auto issue = [&](int c) {
        const int bo = (c % 3) * BUF_B;
        const int go = c * 64;
        cp16(dA + bo, srcA + go);
        cp16(dW0 + bo, srcW0 + go);
        cp16(dW1 + bo, srcW1 + go);
    };

    GDC_WAIT();
    issue(0); CP_COMMIT();
    if (nCh > 1) issue(1);
    CP_COMMIT();

    const int arow = lane & 15;
    const int acolh = (lane >> 4) << 3;
    const int bnt2 = lane >> 4;
    const int bkh = (lane >> 3) & 1;
    const int brow = lane & 7;

    for (int c = 0; c < nCh; c++) {
        cp_wait<1>();
        __syncthreads();
        if (c + 2 < nCh) issue(c + 2);
        CP_COMMIT();

        const uint32_t bo = sbase + (c % 3) * BUF_B;
        const uint32_t uA = bo, uB = bo + TILE_A_B;

        uint32_t ah[2][2][4], bh[2][4][2];
        #pragma unroll
        for (int ks = 0; ks < 2; ks++) {
            const int k0 = ks * 16;
            #pragma unroll
            for (int mt = 0; mt < 2; mt++) {
                uint32_t off = (uint32_t)((wr * 32 + mt * 16 + arow) * PITCH + k0 + acolh) * 2;
                ldsm_x4(ah[ks][mt], uA + off);
            }
            #pragma unroll
            for (int ntp = 0; ntp < 2; ntp++) {
                uint32_t off = (uint32_t)((wc * 32 + (ntp * 2 + bnt2) * 8 + brow) * PITCH
                                          + k0 + bkh * 8) * 2;
                ldsm_x4(&bh[ks][ntp * 2][0], uB + off);
            }
        }
        #pragma unroll
        for (int ks = 0; ks < 2; ks++)
            #pragma unroll
            for (int mt = 0; mt < 2; mt++)
                #pragma unroll
                for (int nt = 0; nt < 4; nt++)
                    mma_f16(acc[mt][nt], ah[ks][mt], bh[ks][nt]);
    }

    #pragma unroll
    for (int mt = 0; mt < 2; mt++) {
        #pragma unroll
        for (int half_ = 0; half_ < 2; half_++) {
            const int r = row0 + wr * 32 + mt * 16 + (lane >> 2) + half_ * 8;
            const float* gt = nullptr;
            const float* rs = nullptr;
            if (EPI >= 2) {
                int b = r / (HGT * WID);
                int rem = r % (HGT * WID);
                int hh = rem / WID, ww = rem % WID;
                gt = gate + (b * 36 + (hh >> 3) * 6 + (ww >> 3)) * 384;
                rs = res + (size_t)r * 384;
            }
            #pragma unroll
            for (int nt = 0; nt < 4; nt++) {
                const int cc = col0 + wc * 32 + nt * 8 + (lane & 3) * 2;
                float v0 = acc[mt][nt][half_ * 2 + 0] + bias[cc];
                float v1 = acc[mt][nt][half_ * 2 + 1] + bias[cc + 1];
                if (EPI == 1) {
                    float x3 = v0 * v0 * v0;
                    v0 = 0.5f * v0 * (1.0f + tanh_fast(0.7978845608028654f * (v0 + 0.044715f * x3)));
                    x3 = v1 * v1 * v1;
                    v1 = 0.5f * v1 * (1.0f + tanh_fast(0.7978845608028654f * (v1 + 0.044715f * x3)));
                }
                if (EPI <= 1) {
                    *(__half2*)(Oh + (size_t)r * M + cc) = __floats2half2_rn(v0, v1);
                } else {
                    float2 o;
                    o.x = rs[cc]     + v0 * gt[cc];
                    o.y = rs[cc + 1] + v1 * gt[cc + 1];
                    *(float2*)(C + (size_t)r * 384 + cc) = o;
                }
            }
        }
    }
}

// ================= tiled neighborhood attention (fp16 smem) ====================
#define NPITCH 68
#define NAT_KVH (196 * NPITCH)
#define NAT_SK 0
#define NAT_SV (NAT_KVH * 2)
#define NAT_SQ (NAT_SV + NAT_KVH * 2)
#define NAT_SW (NAT_SQ + 8 * 128)
#define NAT_SMEM (NAT_SW + 8 * 256)

__global__ void __launch_bounds__(256) natten_k() {
    extern __shared__ char nsm[];
    __half* sK = (__half*)(nsm + NAT_SK);
    __half* sV = (__half*)(nsm + NAT_SV);

    const int tile = blockIdx.x;
    const int head = blockIdx.y;
    const int b = tile / 36;
    const int trm = tile % 36;
    const int t0h = (trm / 6) * 8;
    const int t0w = (trm % 6) * 8;
    const int rlo = max(0, t0h - 3);
    const int rhi = min(HGT - 1, t0h + 10);
    const int clo = max(0, t0w - 3);
    const int chi = min(WID - 1, t0w + 10);
    const int nr = rhi - rlo + 1;
    const int nc = chi - clo + 1;

    GDC_WAIT();
    const int tid = threadIdx.x;
    const int tot = nr * nc * 32;
    for (int i = tid; i < tot; i += 256) {
        int li = i >> 5;
        int d2 = (i & 31);
        int row = li / nc, col = li % nc;
        size_t gbase = (size_t)((b * HGT + rlo + row) * WID + clo + col) * 1152 + head * HD + d2 * 2;
        int so = (row * 14 + col) * NPITCH + d2 * 2;
        *(__half2*)(sK + so) = *(const __half2*)(g_qkvh + gbase + 384);
        *(__half2*)(sV + so) = *(const __half2*)(g_qkvh + gbase + 768);
    }
    __syncthreads();

    const int wid = tid >> 5;
    const int lane = tid & 31;
    __half* q = (__half*)(nsm + NAT_SQ + wid * 128);
    float* wb = (float*)(nsm + NAT_SW + wid * 256);
    const int off1 = (lane / 7) * 14 + lane % 7;
    const int nb2 = lane + 32;
    const int off2 = (nb2 / 7) * 14 + nb2 % 7;
    const bool v2ok = nb2 < 49;

    for (int tt = wid * 8; tt < wid * 8 + 8; tt++) {
        const int tr = tt >> 3, tc = tt & 7;
        const int gr = t0h + tr, gc = t0w + tc;
        const int t = (b * HGT + gr) * WID + gc;
        const int sh = min(max(gr - 3, 0), HGT - 7) - rlo;
        const int sw = min(max(gc - 3, 0), WID - 7) - clo;
        const int base = sh * 14 + sw;

        *(__half2*)(q + lane * 2) = *(const __half2*)(g_qkvh + (size_t)t * 1152 + head * HD + lane * 2);
        __syncwarp();

        float a1 = 0.0f, a2 = 0.0f;
        const uint2* qv = (const uint2*)q;
        const uint2* k1 = (const uint2*)(sK + (base + off1) * NPITCH);
        const uint2* k2 = (const uint2*)(sK + (base + off2) * NPITCH);
        #pragma unroll
        for (int d = 0; d < 16; d++) {
            uint2 qu = qv[d];
            uint2 u1 = k1[d];
            uint2 u2 = k2[d];
            float2 qa = __half22float2(*(const __half2*)&qu.x);
            float2 qb = __half22float2(*(const __half2*)&qu.y);
            float2 x1a = __half22float2(*(const __half2*)&u1.x);
            float2 x1b = __half22float2(*(const __half2*)&u1.y);
            float2 x2a = __half22float2(*(const __half2*)&u2.x);
            float2 x2b = __half22float2(*(const __half2*)&u2.y);
            a1 += qa.x * x1a.x + qa.y * x1a.y + qb.x * x1b.x + qb.y * x1b.y;
            a2 += qa.x * x2a.x + qa.y * x2a.y + qb.x * x2b.x + qb.y * x2b.y;
        }
        a1 *= 0.125f;
        a2 = v2ok ? a2 * 0.125f : -1e30f;

        float m = fmaxf(a1, a2);
        #pragma unroll
        for (int o = 16; o; o >>= 1) m = fmaxf(m, __shfl_xor_sync(0xffffffffu, m, o));
        float e1 = __expf(a1 - m);
        float e2 = v2ok ? __expf(a2 - m) : 0.0f;
        float s = e1 + e2;
        #pragma unroll
        for (int o = 16; o; o >>= 1) s += __shfl_xor_sync(0xffffffffu, s, o);
        float inv = 1.0f / s;
        wb[lane] = e1;
        wb[32 + lane] = e2;
        __syncwarp();

        float o0 = 0.0f, o1 = 0.0f;
        #pragma unroll
        for (int nb = 0; nb < 49; nb++) {
            const int off = (nb / 7) * 14 + nb % 7;
            float wv = wb[nb];
            float2 vv = __half22float2(*(const __half2*)(sV + (base + off) * NPITCH + lane * 2));
            o0 += wv * vv.x;
            o1 += wv * vv.y;
        }
        o0 *= inv; o1 *= inv;
        *(__half2*)(g_attn + (size_t)t * DIM + head * HD + lane * 2) = __floats2half2_rn(o0, o1);
        __syncwarp();
    }
}

// ---------------- launch ------------------------------------------------------
template <typename F, typename... Args>
static void launch_pdl(F f, dim3 g, dim3 b, size_t smem, Args... args) {
    cudaLaunchConfig_t cfg = {};
    cfg.gridDim = g;
    cfg.blockDim = b;
    cfg.dynamicSmemBytes = smem;
    cfg.stream = 0;
    cudaLaunchAttribute at[1];
    at[0].id = cudaLaunchAttributeProgrammaticStreamSerialization;
    at[0].val.programmaticStreamSerializationAllowed = 1;
    cfg.attrs = at;
    cfg.numAttrs = 1;
    cudaLaunchKernelEx(&cfg, f, args...);
}

extern "C" void kernel_launch(void* const* d_in, const int* in_sizes, int n_in,
                              void* d_out, int out_size) {
    const float* x       = (const float*)d_in[0];
    const float* cond    = (const float*)d_in[1];
    const float* ln1_g   = (const float*)d_in[2];
    const float* ln1_b   = (const float*)d_in[3];
    const float* ada1_v  = (const float*)d_in[4];
    const float* ada1_g  = (const float*)d_in[5];
    const float* ln2_g   = (const float*)d_in[6];
    const float* ln2_b   = (const float*)d_in[7];
    const float* ada2_v  = (const float*)d_in[8];
    const float* ada2_g  = (const float*)d_in[9];
    const float* gate1_v = (const float*)d_in[10];
    const float* gate1_g = (const float*)d_in[11];
    const float* gate2_v = (const float*)d_in[12];
    const float* gate2_g = (const float*)d_in[13];
    const float* w_qkv   = (const float*)d_in[14];
    const float* b_qkv   = (const float*)d_in[15];
    const float* w_out   = (const float*)d_in[16];
    const float* b_out   = (const float*)d_in[17];
    const float* w_mlp1  = (const float*)d_in[18];
    const float* b_mlp1  = (const float*)d_in[19];
    const float* w_mlp2  = (const float*)d_in[20];
    const float* b_mlp2  = (const float*)d_in[21];
    float* out = (float*)d_out;

    float *p_ab1, *p_g1, *p_ab2, *p_g2, *p_x;
    __half *p_h, *p_qkvh, *p_attn, *p_mlp, *p_wq, *p_wo, *p_w1, *p_w2;
    cudaGetSymbolAddress((void**)&p_ab1, g_ab1);
    cudaGetSymbolAddress((void**)&p_ab2, g_ab2);
    cudaGetSymbolAddress((void**)&p_g1, g_g1);
    cudaGetSymbolAddress((void**)&p_g2, g_g2);
    cudaGetSymbolAddress((void**)&p_x, g_x);
    cudaGetSymbolAddress((void**)&p_h, g_h);
    cudaGetSymbolAddress((void**)&p_qkvh, g_qkvh);
    cudaGetSymbolAddress((void**)&p_attn, g_attn);
    cudaGetSymbolAddress((void**)&p_mlp, g_mlp);
    cudaGetSymbolAddress((void**)&p_wq, g_wqkv);
    cudaGetSymbolAddress((void**)&p_wo, g_wout);
    cudaGetSymbolAddress((void**)&p_w1, g_wm1);
    cudaGetSymbolAddress((void**)&p_w2, g_wm2);

    cudaFuncSetAttribute(prep_k, cudaFuncAttributeMaxDynamicSharedMemorySize, PREP_SMEM);
    cudaFuncSetAttribute(hgemm_k<0>, cudaFuncAttributeMaxDynamicSharedMemorySize, SMEM_TOT);
    cudaFuncSetAttribute(hgemm_k<1>, cudaFuncAttributeMaxDynamicSharedMemorySize, SMEM_TOT);
    cudaFuncSetAttribute(hgemm_k<2>, cudaFuncAttributeMaxDynamicSharedMemorySize, SMEM_TOT);
    cudaFuncSetAttribute(hgemm_k<3>, cudaFuncAttributeMaxDynamicSharedMemorySize, SMEM_TOT);
    cudaFuncSetAttribute(natten_k, cudaFuncAttributeMaxDynamicSharedMemorySize, NAT_SMEM);

    prep_k<<<72 + 432, 256, PREP_SMEM>>>(cond, ada1_v, ada1_g, ada2_v, ada2_g,
                                         gate1_v, gate1_g, gate2_v, gate2_g,
                                         w_qkv, w_out, w_mlp1, w_mlp2);

    const float* nullf = nullptr;
    __half* nullh = nullptr;

    launch_pdl(adaln_k, dim3(NTOK / 8), dim3(256), 0, x, ln1_g, ln1_b, (const float*)p_ab1);
    launch_pdl(hgemm_k<0>, dim3(1152 / 128, NTOK / 64), dim3(256), (size_t)SMEM_TOT,
               (const __half*)p_h, (const __half*)p_wq, b_qkv, (float*)nullptr, 384, 1152,
               nullf, nullf, p_qkvh);
    launch_pdl(natten_k, dim3(72, NHEAD), dim3(256), (size_t)NAT_SMEM);
    launch_pdl(hgemm_k<2>, dim3(384 / 128, NTOK / 64), dim3(256), (size_t)SMEM_TOT,
               (const __half*)p_attn, (const __half*)p_wo, b_out, p_x, 384, 384,
               x, (const float*)p_g1, nullh);
    launch_pdl(adaln_k, dim3(NTOK / 8), dim3(256), 0, (const float*)p_x, ln2_g, ln2_b,
               (const float*)p_ab2);
    launch_pdl(hgemm_k<1>, dim3(1536 / 128, NTOK / 64), dim3(256), (size_t)SMEM_TOT,
               (const __half*)p_h, (const __half*)p_w1, b_mlp1, (float*)nullptr, 384, 1536,
               nullf, nullf, p_mlp);
    launch_pdl(hgemm_k<3>, dim3(384 / 128, NTOK / 64), dim3(256), (size_t)SMEM_TOT,
               (const __half*)p_mlp, (const __half*)p_w2, b_mlp2, out, 1536, 384,
               (const float*)p_x, (const float*)p_g2, nullh);
}